// round 12
// baseline (speedup 1.0000x reference)
#include <cuda_runtime.h>
#include <cstdint>

// ---------------------------------------------------------------------------
// Problem constants
// ---------------------------------------------------------------------------
#define DMODEL 1024
#define NHEADS 16
#define HD     64
#define BATCH  2
#define TSEQ   2048
#define BT     4096
#define NROWS  65536
#define OUT_ELEMS 4194304LL
#define QKV_ELEMS (32 * 2048 * 64)      // 4194304 elements per split array

// Scratch (static device memory; allocation APIs are forbidden)
__device__ __align__(16) unsigned short g_Qh[QKV_ELEMS];   // (z,t,64) bf16 hi
__device__ __align__(16) unsigned short g_Ql[QKV_ELEMS];   // lo
__device__ __align__(16) unsigned short g_Kh[QKV_ELEMS];
__device__ __align__(16) unsigned short g_Kl[QKV_ELEMS];
__device__ __align__(16) unsigned short g_Vth[QKV_ELEMS];  // (z,c,t) bf16 hi (V transposed)
__device__ __align__(16) unsigned short g_Vtl[QKV_ELEMS];
__device__ __align__(16) unsigned short g_Xh[BT * DMODEL];   // x split
__device__ __align__(16) unsigned short g_Xl[BT * DMODEL];
__device__ __align__(16) unsigned short g_Wh[4 * 1024 * 1024]; // WQ|WK|WV|WO split
__device__ __align__(16) unsigned short g_Wl[4 * 1024 * 1024];
__device__ __align__(16) unsigned short g_Oh[BT * DMODEL];   // attention O split
__device__ __align__(16) unsigned short g_Ol[BT * DMODEL];
__device__ float g_inv[NROWS];

// ---------------------------------------------------------------------------
// helpers
// ---------------------------------------------------------------------------
__device__ __forceinline__ uint32_t smem_u32(const void* p) {
    uint32_t a;
    asm("{ .reg .u64 t; cvta.to.shared.u64 t, %1; cvt.u32.u64 %0, t; }" : "=r"(a) : "l"(p));
    return a;
}
__device__ __forceinline__ void cvt2(float x0, float x1, uint32_t& hp, uint32_t& lp) {
    asm("cvt.rn.bf16x2.f32 %0, %1, %2;" : "=r"(hp) : "f"(x1), "f"(x0));
    float h0 = __uint_as_float(hp << 16);
    float h1 = __uint_as_float(hp & 0xFFFF0000u);
    asm("cvt.rn.bf16x2.f32 %0, %1, %2;" : "=r"(lp) : "f"(x1 - h1), "f"(x0 - h0));
}
__device__ __forceinline__ void mma_bf16(float* c, const uint32_t* a, const uint32_t* b) {
    asm volatile(
        "mma.sync.aligned.m16n8k16.row.col.f32.bf16.bf16.f32 "
        "{%0,%1,%2,%3}, {%4,%5,%6,%7}, {%8,%9}, {%0,%1,%2,%3};"
        : "+f"(c[0]), "+f"(c[1]), "+f"(c[2]), "+f"(c[3])
        : "r"(a[0]), "r"(a[1]), "r"(a[2]), "r"(a[3]), "r"(b[0]), "r"(b[1]));
}
__device__ __forceinline__ void ldsm4(uint32_t* r, uint32_t addr) {
    asm volatile("ldmatrix.sync.aligned.m8n8.x4.shared.b16 {%0,%1,%2,%3}, [%4];"
                 : "=r"(r[0]), "=r"(r[1]), "=r"(r[2]), "=r"(r[3]) : "r"(addr));
}
__device__ __forceinline__ void cpa(uint32_t d, const unsigned short* s) {
    asm volatile("cp.async.ca.shared.global [%0], [%1], 16;"
                 :: "r"(d), "l"(__cvta_generic_to_global(s)) : "memory");
}
#define CP_COMMIT() asm volatile("cp.async.commit_group;" ::: "memory")
#define CP_WAIT0()  asm volatile("cp.async.wait_group 0;" ::: "memory")
#define CP_WAIT1()  asm volatile("cp.async.wait_group 1;" ::: "memory")
#define CP_WAIT2()  asm volatile("cp.async.wait_group 2;" ::: "memory")

// ---------------------------------------------------------------------------
// Elementwise fp32 -> bf16 hi/lo split (preconversion for GEMM operands)
// ---------------------------------------------------------------------------
__global__ __launch_bounds__(256) void split_bf16(
    const float* __restrict__ src, unsigned short* __restrict__ dh,
    unsigned short* __restrict__ dl, int n4)
{
    const int i = blockIdx.x * 256 + threadIdx.x;
    if (i < n4) {
        float4 v = ((const float4*)src)[i];
        uint32_t h01, l01, h23, l23;
        cvt2(v.x, v.y, h01, l01);
        cvt2(v.z, v.w, h23, l23);
        ((uint2*)dh)[i] = make_uint2(h01, h23);
        ((uint2*)dl)[i] = make_uint2(l01, l23);
    }
}

// ---------------------------------------------------------------------------
// Attention passes (preconverted bf16 operands, cp.async, ldmatrix).
// PASS 1: single-term bf16 S; row sums of E -> g_inv.
// PASS 2: bf16x3 S; W=E*inv written ONCE to wts; O += W*V chained in regs;
//         O written as split bf16 (g_Oh/g_Ol).
// Grid (16 m-tiles, 32 z). 256 thr, warps 4(m) x 2(n). n-tile = 64.
// ---------------------------------------------------------------------------
template <int PASS>
__global__ __launch_bounds__(256) void attn_kernel(
    const unsigned short* __restrict__ Qhg, const unsigned short* __restrict__ Qlg,
    const unsigned short* __restrict__ Khg, const unsigned short* __restrict__ Klg,
    const unsigned short* __restrict__ Vhg, const unsigned short* __restrict__ Vlg,
    const int* __restrict__ mask, float* __restrict__ wts,
    float* __restrict__ invp)
{
    extern __shared__ char smraw[];
    const uint32_t sb = smem_u32(smraw);
    constexpr uint32_t QH = 0;
    constexpr uint32_t QL = 18432;                               // pass2 only
    constexpr uint32_t KB = (PASS == 1) ? 18432u : 36864u;
    constexpr uint32_t KSTR = (PASS == 1) ? 9216u : 18432u;
    constexpr uint32_t VB = 73728;                               // pass2 only
    constexpr uint32_t MK = (PASS == 1) ? 36864u : 110592u;
    __shared__ float rsc[256];

    const int tid = threadIdx.x, lane = tid & 31, wid = tid >> 5;
    const int g = lane >> 2, t4 = lane & 3;
    const int wm0 = (wid >> 1) * 32, wni = wid & 1;
    const int z = blockIdx.y, m0 = blockIdx.x * 128, gb = z >> 4;
    const long long zo = (long long)z * (2048 * 64);
    const long long TT = 2048LL * 2048;

    unsigned char* mk8 = (unsigned char*)(smraw + MK);
    for (int i = tid; i < 2048; i += 256)
        mk8[i] = mask[gb * 2048 + i] ? 0 : 1;

    const uint32_t aRow = (uint32_t)(lane & 15);
    const uint32_t aColB = (uint32_t)((lane >> 4) * 16);
    const uint32_t bRow = (uint32_t)(((lane >> 4) & 1) * 8 + (lane & 7));
    const uint32_t bColB = (uint32_t)(((lane >> 3) & 1) * 16);

#pragma unroll
    for (int i = 0; i < 4; ++i) {
        const int idx = tid + 256 * i, r = idx >> 3, q = idx & 7;
        const long long so = zo + (long long)(m0 + r) * 64 + 8 * q;
        cpa(sb + QH + r * 144 + q * 16, Qhg + so);
        if (PASS == 2) cpa(sb + QL + r * 144 + q * 16, Qlg + so);
    }

    auto issueK = [&](int nt, int buf) {
        const uint32_t kb = sb + KB + (uint32_t)buf * KSTR;
#pragma unroll
        for (int i = 0; i < 2; ++i) {
            const int idx = tid + 256 * i, r = idx >> 3, q = idx & 7;
            const long long so = zo + (long long)(nt * 64 + r) * 64 + 8 * q;
            cpa(kb + r * 144 + q * 16, Khg + so);
            if (PASS == 2) cpa(kb + 9216 + r * 144 + q * 16, Klg + so);
        }
    };
    auto issueV = [&](int nt, int buf) {
        const uint32_t vb = sb + VB + (uint32_t)buf * 18432;
#pragma unroll
        for (int i = 0; i < 2; ++i) {
            const int idx = tid + 256 * i, c = idx >> 3, q = idx & 7;
            const long long so = (long long)(z * 64 + c) * 2048 + nt * 64 + 8 * q;
            cpa(vb + c * 144 + q * 16, Vhg + so);
            cpa(vb + 9216 + c * 144 + q * 16, Vlg + so);
        }
    };

    float iv[2][2];
    float oacc[2][8][4];
    float rs[2][2] = {{0.f, 0.f}, {0.f, 0.f}};
    if (PASS == 2) {
#pragma unroll
        for (int mi = 0; mi < 2; ++mi) {
            iv[mi][0] = invp[z * 2048 + m0 + wm0 + 16 * mi + g];
            iv[mi][1] = invp[z * 2048 + m0 + wm0 + 16 * mi + g + 8];
        }
#pragma unroll
        for (int mi = 0; mi < 2; ++mi)
#pragma unroll
            for (int cf = 0; cf < 8; ++cf)
#pragma unroll
                for (int j = 0; j < 4; ++j) oacc[mi][cf][j] = 0.f;
    }

    issueK(0, 0);
    if (PASS == 2) issueV(0, 0);
    CP_COMMIT();

    for (int nt = 0; nt < 32; ++nt) {
        const int buf = nt & 1;
        if (nt < 31) {
            issueK(nt + 1, buf ^ 1);
            if (PASS == 2) issueV(nt + 1, buf ^ 1);
            CP_COMMIT();
            CP_WAIT1();
        } else {
            CP_WAIT0();
        }
        __syncthreads();

        const uint32_t kh = sb + KB + (uint32_t)buf * KSTR;
        const uint32_t kl = kh + 9216;

        float sacc[2][4][4];
#pragma unroll
        for (int mi = 0; mi < 2; ++mi)
#pragma unroll
            for (int nf = 0; nf < 4; ++nf)
#pragma unroll
                for (int j = 0; j < 4; ++j) sacc[mi][nf][j] = 0.f;

#pragma unroll
        for (int ks = 0; ks < 4; ++ks) {
            const uint32_t ac = (uint32_t)(ks * 32) + aColB;
            const uint32_t bc = (uint32_t)(ks * 32) + bColB;
            uint32_t a0h[4], a1h[4], b0h[4], b1h[4];
            ldsm4(a0h, sb + QH + (wm0 + aRow) * 144 + ac);
            ldsm4(a1h, sb + QH + (wm0 + 16 + aRow) * 144 + ac);
            ldsm4(b0h, kh + (wni * 32 + bRow) * 144 + bc);
            ldsm4(b1h, kh + (wni * 32 + 16 + bRow) * 144 + bc);
            mma_bf16(sacc[0][0], a0h, b0h); mma_bf16(sacc[0][1], a0h, b0h + 2);
            mma_bf16(sacc[0][2], a0h, b1h); mma_bf16(sacc[0][3], a0h, b1h + 2);
            mma_bf16(sacc[1][0], a1h, b0h); mma_bf16(sacc[1][1], a1h, b0h + 2);
            mma_bf16(sacc[1][2], a1h, b1h); mma_bf16(sacc[1][3], a1h, b1h + 2);
            if (PASS == 2) {
                uint32_t a0l[4], a1l[4], b0l[4], b1l[4];
                ldsm4(a0l, sb + QL + (wm0 + aRow) * 144 + ac);
                ldsm4(a1l, sb + QL + (wm0 + 16 + aRow) * 144 + ac);
                ldsm4(b0l, kl + (wni * 32 + bRow) * 144 + bc);
                ldsm4(b1l, kl + (wni * 32 + 16 + bRow) * 144 + bc);
                mma_bf16(sacc[0][0], a0h, b0l); mma_bf16(sacc[0][1], a0h, b0l + 2);
                mma_bf16(sacc[0][2], a0h, b1l); mma_bf16(sacc[0][3], a0h, b1l + 2);
                mma_bf16(sacc[1][0], a1h, b0l); mma_bf16(sacc[1][1], a1h, b0l + 2);
                mma_bf16(sacc[1][2], a1h, b1l); mma_bf16(sacc[1][3], a1h, b1l + 2);
                mma_bf16(sacc[0][0], a0l, b0h); mma_bf16(sacc[0][1], a0l, b0h + 2);
                mma_bf16(sacc[0][2], a0l, b1h); mma_bf16(sacc[0][3], a0l, b1h + 2);
                mma_bf16(sacc[1][0], a1l, b0h); mma_bf16(sacc[1][1], a1l, b0h + 2);
                mma_bf16(sacc[1][2], a1l, b1h); mma_bf16(sacc[1][3], a1l, b1h + 2);
            }
        }

        if (PASS == 1) {
#pragma unroll
            for (int mi = 0; mi < 2; ++mi)
#pragma unroll
                for (int nf = 0; nf < 4; ++nf) {
                    const int n = nt * 64 + wni * 32 + 8 * nf + 2 * t4;
                    const float f0 = (float)mk8[n], f1 = (float)mk8[n + 1];
                    rs[mi][0] += f0 * __expf(0.125f * sacc[mi][nf][0])
                               + f1 * __expf(0.125f * sacc[mi][nf][1]);
                    rs[mi][1] += f0 * __expf(0.125f * sacc[mi][nf][2])
                               + f1 * __expf(0.125f * sacc[mi][nf][3]);
                }
        } else {
            const uint32_t vh = sb + VB + (uint32_t)buf * 18432;
            const uint32_t vl = vh + 9216;
#pragma unroll
            for (int kv = 0; kv < 2; ++kv) {
                uint32_t wh[2][4], wl[2][4];
#pragma unroll
                for (int mi = 0; mi < 2; ++mi) {
#pragma unroll
                    for (int j = 0; j < 2; ++j) {
                        const int nf = 2 * kv + j;
                        const int n = nt * 64 + wni * 32 + 8 * nf + 2 * t4;
                        const float f0 = (float)mk8[n], f1 = (float)mk8[n + 1];
                        const float w0 = f0 * __expf(0.125f * sacc[mi][nf][0]) * iv[mi][0];
                        const float w1 = f1 * __expf(0.125f * sacc[mi][nf][1]) * iv[mi][0];
                        const float w2 = f0 * __expf(0.125f * sacc[mi][nf][2]) * iv[mi][1];
                        const float w3 = f1 * __expf(0.125f * sacc[mi][nf][3]) * iv[mi][1];
                        const int r0 = m0 + wm0 + 16 * mi + g;
                        float* Wp = wts + (long long)z * TT + (long long)r0 * 2048 + n;
                        *(float2*)Wp = make_float2(w0, w1);
                        *(float2*)(Wp + 8LL * 2048) = make_float2(w2, w3);
                        cvt2(w0, w1, wh[mi][2 * j], wl[mi][2 * j]);
                        cvt2(w2, w3, wh[mi][2 * j + 1], wl[mi][2 * j + 1]);
                    }
                }
                const uint32_t vcb = (uint32_t)(wni * 64 + kv * 32) + bColB;
#pragma unroll
                for (int cfp = 0; cfp < 4; ++cfp) {
                    uint32_t vh4[4], vl4[4];
                    ldsm4(vh4, vh + (cfp * 16 + bRow) * 144 + vcb);
                    ldsm4(vl4, vl + (cfp * 16 + bRow) * 144 + vcb);
#pragma unroll
                    for (int mi = 0; mi < 2; ++mi)
#pragma unroll
                        for (int j = 0; j < 2; ++j) {
                            float* o = oacc[mi][2 * cfp + j];
                            mma_bf16(o, wh[mi], vh4 + 2 * j);
                            mma_bf16(o, wh[mi], vl4 + 2 * j);
                            mma_bf16(o, wl[mi], vh4 + 2 * j);
                        }
                }
            }
        }
        __syncthreads();
    }

    if (PASS == 1) {
#pragma unroll
        for (int mi = 0; mi < 2; ++mi)
#pragma unroll
            for (int j = 0; j < 2; ++j) {
                float v = rs[mi][j];
                v += __shfl_xor_sync(0xffffffffu, v, 1);
                v += __shfl_xor_sync(0xffffffffu, v, 2);
                if (t4 == 0) rsc[(wm0 + 16 * mi + g + 8 * j) * 2 + wni] = v;
            }
        __syncthreads();
        if (tid < 128) {
            const float s = rsc[tid * 2] + rsc[tid * 2 + 1];
            invp[z * 2048 + m0 + tid] = (s > 0.f) ? (1.f / s) : 0.f;
        }
    } else {
        float* Osc = (float*)(smraw + 36864);   // overlay on K buffers
        if (wni == 0) {
#pragma unroll
            for (int mi = 0; mi < 2; ++mi)
#pragma unroll
                for (int cf = 0; cf < 8; ++cf) {
                    const int r0 = wm0 + 16 * mi + g, c = 8 * cf + 2 * t4;
                    *(float2*)(Osc + r0 * 66 + c) = make_float2(oacc[mi][cf][0], oacc[mi][cf][1]);
                    *(float2*)(Osc + (r0 + 8) * 66 + c) = make_float2(oacc[mi][cf][2], oacc[mi][cf][3]);
                }
        }
        __syncthreads();
        if (wni == 1) {
#pragma unroll
            for (int mi = 0; mi < 2; ++mi)
#pragma unroll
                for (int cf = 0; cf < 8; ++cf) {
                    const int r0 = wm0 + 16 * mi + g, c = 8 * cf + 2 * t4;
                    float2 p0 = *(float2*)(Osc + r0 * 66 + c);
                    float2 p1 = *(float2*)(Osc + (r0 + 8) * 66 + c);
                    const long long b0 = ((long long)(gb * 2048 + m0 + r0)) * 1024 + (z & 15) * 64 + c;
                    const long long b1 = ((long long)(gb * 2048 + m0 + r0 + 8)) * 1024 + (z & 15) * 64 + c;
                    uint32_t h01, l01, h23, l23;
                    cvt2(p0.x + oacc[mi][cf][0], p0.y + oacc[mi][cf][1], h01, l01);
                    cvt2(p1.x + oacc[mi][cf][2], p1.y + oacc[mi][cf][3], h23, l23);
                    *(uint32_t*)&g_Oh[b0] = h01; *(uint32_t*)&g_Ol[b0] = l01;
                    *(uint32_t*)&g_Oh[b1] = h23; *(uint32_t*)&g_Ol[b1] = l23;
                }
        }
    }
}

// ---------------------------------------------------------------------------
// bf16x3 GEMM on preconverted split operands. cp.async, 3-stage pipeline,
// 512 threads / 16 warps (4m x 4n), CTA tile 128x128, warp tile 32x32,
// k-chunk 32.  C = A(M,K) * B(N,K)^T.
// EPI 0: plain fp32 store (out-proj).  EPI 1: QKV routing -> split arrays.
// SMEM stage (40960 B): Ah@0, Al@10240, Bh@20480, Bl@30720; 80-B rows.
// ---------------------------------------------------------------------------
template <int EPI>
__global__ __launch_bounds__(512, 1) void gemm_cp(
    const unsigned short* __restrict__ Ahg, const unsigned short* __restrict__ Alg,
    const unsigned short* __restrict__ Bhg, const unsigned short* __restrict__ Blg,
    float* __restrict__ C, int ldc, int Kd)
{
    extern __shared__ char smg[];
    const uint32_t sb = smem_u32(smg);

    const int tid = threadIdx.x, lane = tid & 31, wid = tid >> 5;
    const int g = lane >> 2, t4 = lane & 3;
    const int wm0 = (wid >> 2) * 32;
    const int wn0 = (wid & 3) * 32;
    const int m0 = blockIdx.y * 128, n0 = blockIdx.x * 128;

    const uint32_t aRow = (uint32_t)(lane & 15);
    const uint32_t aColB = (uint32_t)((lane >> 4) * 16);
    const uint32_t bRow = (uint32_t)(((lane >> 4) & 1) * 8 + (lane & 7));
    const uint32_t bColB = (uint32_t)(((lane >> 3) & 1) * 16);

    const unsigned short *Bh0, *Bl0;
    if (EPI == 1) {
        const int mat = blockIdx.x >> 3;
        const long long off = (long long)mat * 1048576 + (long long)((blockIdx.x & 7) * 128) * 1024;
        Bh0 = Bhg + off; Bl0 = Blg + off;
    } else {
        Bh0 = Bhg + (long long)n0 * 1024;
        Bl0 = Blg + (long long)n0 * 1024;
    }

    float acc[2][4][4];
#pragma unroll
    for (int mi = 0; mi < 2; ++mi)
#pragma unroll
        for (int ni = 0; ni < 4; ++ni)
#pragma unroll
            for (int j = 0; j < 4; ++j) acc[mi][ni][j] = 0.f;

    const int lr = tid >> 2, lq = tid & 3;      // 128 rows x 4 chunks of 16B
    auto issue = [&](int s, int buf) {
        const uint32_t base = sb + (uint32_t)buf * 40960;
        const long long ao = (long long)(m0 + lr) * 1024 + s * 32 + 8 * lq;
        const long long bo = (long long)lr * 1024 + s * 32 + 8 * lq;
        const uint32_t d = lr * 80 + lq * 16;
        cpa(base + d,         Ahg + ao);
        cpa(base + 10240 + d, Alg + ao);
        cpa(base + 20480 + d, Bh0 + bo);
        cpa(base + 30720 + d, Bl0 + bo);
    };

    auto compute = [&](int buf) {
        const uint32_t AhB = sb + (uint32_t)buf * 40960;
        const uint32_t AlB = AhB + 10240;
        const uint32_t BhB = AhB + 20480;
        const uint32_t BlB = AhB + 30720;
#pragma unroll
        for (int ks = 0; ks < 2; ++ks) {
            const uint32_t ac = (uint32_t)(ks * 32) + aColB;
            const uint32_t bc = (uint32_t)(ks * 32) + bColB;
            uint32_t ah[2][4], al[2][4];
#pragma unroll
            for (int mi = 0; mi < 2; ++mi) {
                ldsm4(ah[mi], AhB + (wm0 + 16 * mi + aRow) * 80 + ac);
                ldsm4(al[mi], AlB + (wm0 + 16 * mi + aRow) * 80 + ac);
            }
#pragma unroll
            for (int nfp = 0; nfp < 2; ++nfp) {
                uint32_t bh4[4], bl4[4];
                ldsm4(bh4, BhB + (wn0 + nfp * 16 + bRow) * 80 + bc);
                ldsm4(bl4, BlB + (wn0 + nfp * 16 + bRow) * 80 + bc);
#pragma unroll
                for (int mi = 0; mi < 2; ++mi)
#pragma unroll
                    for (int j = 0; j < 2; ++j) {
                        float* o = acc[mi][2 * nfp + j];
                        mma_bf16(o, ah[mi], bh4 + 2 * j);
                        mma_bf16(o, ah[mi], bl4 + 2 * j);
                        mma_bf16(o, al[mi], bh4 + 2 * j);
                    }
            }
        }
    };

    const int nS = Kd >> 5;
    issue(0, 0); CP_COMMIT();
    issue(1, 1); CP_COMMIT();
    for (int s = 0; s < nS; ++s) {
        if (s + 2 < nS) {
            issue(s + 2, (s + 2) % 3);
            CP_COMMIT();
            CP_WAIT2();
        } else if (s + 1 < nS) {
            CP_WAIT1();
        } else {
            CP_WAIT0();
        }
        __syncthreads();
        compute(s % 3);
        __syncthreads();
    }

#pragma unroll
    for (int mi = 0; mi < 2; ++mi) {
        const int r0 = wm0 + 16 * mi + g, r1 = r0 + 8;
#pragma unroll
        for (int ni = 0; ni < 4; ++ni) {
            const int c = wn0 + 8 * ni + 2 * t4;
            const float v0 = acc[mi][ni][0], v1 = acc[mi][ni][1];
            const float v2 = acc[mi][ni][2], v3 = acc[mi][ni][3];
            if (EPI == 0) {
                *(float2*)(C + (long long)(m0 + r0) * ldc + n0 + c) = make_float2(v0, v1);
                *(float2*)(C + (long long)(m0 + r1) * ldc + n0 + c) = make_float2(v2, v3);
            } else {
                const int nloc = (blockIdx.x & 7) * 128 + c;
                const int h = nloc >> 6, k = nloc & 63;
                const int mat = blockIdx.x >> 3;
                const int mr0 = m0 + r0, b0 = mr0 >> 11, tt0 = mr0 & 2047;
                const int mr1 = m0 + r1, b1 = mr1 >> 11, tt1 = mr1 & 2047;
                uint32_t h01, l01, h23, l23;
                cvt2(v0, v1, h01, l01);
                cvt2(v2, v3, h23, l23);
                if (mat < 2) {
                    unsigned short* dh = (mat == 0) ? g_Qh : g_Kh;
                    unsigned short* dl = (mat == 0) ? g_Ql : g_Kl;
                    const long long o0 = ((long long)((b0 * 16 + h) * 2048 + tt0)) * 64 + k;
                    const long long o1 = ((long long)((b1 * 16 + h) * 2048 + tt1)) * 64 + k;
                    *(uint32_t*)&dh[o0] = h01; *(uint32_t*)&dl[o0] = l01;
                    *(uint32_t*)&dh[o1] = h23; *(uint32_t*)&dl[o1] = l23;
                } else {
                    const long long c0 = ((long long)((b0 * 16 + h) * 64 + k)) * 2048;
                    const long long c1 = c0 + 2048;
                    g_Vth[c0 + tt0] = (unsigned short)(h01 & 0xFFFF);
                    g_Vth[c1 + tt0] = (unsigned short)(h01 >> 16);
                    g_Vtl[c0 + tt0] = (unsigned short)(l01 & 0xFFFF);
                    g_Vtl[c1 + tt0] = (unsigned short)(l01 >> 16);
                    g_Vth[c0 + tt1] = (unsigned short)(h23 & 0xFFFF);
                    g_Vth[c1 + tt1] = (unsigned short)(h23 >> 16);
                    g_Vtl[c0 + tt1] = (unsigned short)(l23 & 0xFFFF);
                    g_Vtl[c1 + tt1] = (unsigned short)(l23 >> 16);
                }
            }
        }
    }
}

// ---------------------------------------------------------------------------
// kernel_launch: x, mask(int32), W_Q, W_K, W_V, W_O -> d_out = [output | weights]
// ---------------------------------------------------------------------------
extern "C" void kernel_launch(void* const* d_in, const int* in_sizes, int n_in,
                              void* d_out, int out_size)
{
    const float* x    = (const float*)d_in[0];
    const int*   mask = (const int*)d_in[1];
    const float* WQ   = (const float*)d_in[2];
    const float* WK   = (const float*)d_in[3];
    const float* WV   = (const float*)d_in[4];
    const float* WO   = (const float*)d_in[5];

    float* out = (float*)d_out;
    float* wts = out + OUT_ELEMS;

    unsigned short *Qh, *Ql, *Kh, *Kl, *Vth, *Vtl, *Xh, *Xl, *Wh, *Wl, *Oh, *Ol;
    float *invp;
    cudaGetSymbolAddress((void**)&Qh,  g_Qh);
    cudaGetSymbolAddress((void**)&Ql,  g_Ql);
    cudaGetSymbolAddress((void**)&Kh,  g_Kh);
    cudaGetSymbolAddress((void**)&Kl,  g_Kl);
    cudaGetSymbolAddress((void**)&Vth, g_Vth);
    cudaGetSymbolAddress((void**)&Vtl, g_Vtl);
    cudaGetSymbolAddress((void**)&Xh,  g_Xh);
    cudaGetSymbolAddress((void**)&Xl,  g_Xl);
    cudaGetSymbolAddress((void**)&Wh,  g_Wh);
    cudaGetSymbolAddress((void**)&Wl,  g_Wl);
    cudaGetSymbolAddress((void**)&Oh,  g_Oh);
    cudaGetSymbolAddress((void**)&Ol,  g_Ol);
    cudaGetSymbolAddress((void**)&invp, g_inv);

    const int SMG = 3 * 40960;         // 122880 (gemm_cp)
    const int SM1 = 38912;
    const int SM2 = 112640;
    cudaFuncSetAttribute(gemm_cp<1>, cudaFuncAttributeMaxDynamicSharedMemorySize, SMG);
    cudaFuncSetAttribute(gemm_cp<0>, cudaFuncAttributeMaxDynamicSharedMemorySize, SMG);
    cudaFuncSetAttribute(attn_kernel<1>, cudaFuncAttributeMaxDynamicSharedMemorySize, SM1);
    cudaFuncSetAttribute(attn_kernel<2>, cudaFuncAttributeMaxDynamicSharedMemorySize, SM2);

    // 0) Preconvert GEMM operands to bf16 hi/lo splits
    split_bf16<<<4096, 256>>>(x, Xh, Xl, 1048576);
    split_bf16<<<1024, 256>>>(WQ, Wh,               Wl,               262144);
    split_bf16<<<1024, 256>>>(WK, Wh + 1048576,     Wl + 1048576,     262144);
    split_bf16<<<1024, 256>>>(WV, Wh + 2097152,     Wl + 2097152,     262144);
    split_bf16<<<1024, 256>>>(WO, Wh + 3145728,     Wl + 3145728,     262144);

    // 1) Fused QKV projection -> split Q,K and transposed split V
    gemm_cp<1><<<dim3(24, 32, 1), 512, SMG>>>(
        Xh, Xl, Wh, Wl, nullptr, 0, DMODEL);

    // 2) Pass 1: row sums -> inv (single-term bf16 S, zero TT traffic)
    attn_kernel<1><<<dim3(16, 32), 256, SM1>>>(
        Qh, Ql, Kh, Kl, Vth, Vtl, mask, wts, invp);

    // 3) Pass 2: W written once + O = W*V fused (bf16x3); O stored split bf16
    attn_kernel<2><<<dim3(16, 32), 256, SM2>>>(
        Qh, Ql, Kh, Kl, Vth, Vtl, mask, wts, invp);

    // 4) Output projection from split O
    gemm_cp<0><<<dim3(8, 32, 1), 512, SMG>>>(
        Oh, Ol, Wh + 3145728, Wl + 3145728, out, DMODEL, DMODEL);
}

// round 14
// speedup vs baseline: 1.0586x; 1.0586x over previous
#include <cuda_runtime.h>
#include <cstdint>

// ---------------------------------------------------------------------------
// Problem constants
// ---------------------------------------------------------------------------
#define DMODEL 1024
#define NHEADS 16
#define HD     64
#define BATCH  2
#define TSEQ   2048
#define BT     4096
#define NROWS  65536
#define OUT_ELEMS 4194304LL
#define QKV_ELEMS (32 * 2048 * 64)      // 4194304 elements per split array

// Scratch (static device memory; allocation APIs are forbidden)
__device__ unsigned short g_Qh[QKV_ELEMS];   // (z,t,64) bf16 hi
__device__ unsigned short g_Ql[QKV_ELEMS];   // lo
__device__ unsigned short g_Kh[QKV_ELEMS];
__device__ unsigned short g_Kl[QKV_ELEMS];
__device__ unsigned short g_Vth[QKV_ELEMS];  // (z,c,t) bf16 hi (V transposed)
__device__ unsigned short g_Vtl[QKV_ELEMS];
__device__ float g_O[BT * DMODEL];           // (B,T,H*64) fp32
__device__ float g_inv[NROWS];

// ---------------------------------------------------------------------------
// helpers
// ---------------------------------------------------------------------------
__device__ __forceinline__ uint32_t smem_u32(const void* p) {
    uint32_t a;
    asm("{ .reg .u64 t; cvta.to.shared.u64 t, %1; cvt.u32.u64 %0, t; }" : "=r"(a) : "l"(p));
    return a;
}
__device__ __forceinline__ void cvt2(float x0, float x1, uint32_t& hp, uint32_t& lp) {
    asm("cvt.rn.bf16x2.f32 %0, %1, %2;" : "=r"(hp) : "f"(x1), "f"(x0));
    float h0 = __uint_as_float(hp << 16);
    float h1 = __uint_as_float(hp & 0xFFFF0000u);
    asm("cvt.rn.bf16x2.f32 %0, %1, %2;" : "=r"(lp) : "f"(x1 - h1), "f"(x0 - h0));
}
__device__ __forceinline__ void mma_bf16(float* c, const uint32_t* a, const uint32_t* b) {
    asm volatile(
        "mma.sync.aligned.m16n8k16.row.col.f32.bf16.bf16.f32 "
        "{%0,%1,%2,%3}, {%4,%5,%6,%7}, {%8,%9}, {%0,%1,%2,%3};"
        : "+f"(c[0]), "+f"(c[1]), "+f"(c[2]), "+f"(c[3])
        : "r"(a[0]), "r"(a[1]), "r"(a[2]), "r"(a[3]), "r"(b[0]), "r"(b[1]));
}
__device__ __forceinline__ void ldsm4(uint32_t* r, uint32_t addr) {
    asm volatile("ldmatrix.sync.aligned.m8n8.x4.shared.b16 {%0,%1,%2,%3}, [%4];"
                 : "=r"(r[0]), "=r"(r[1]), "=r"(r[2]), "=r"(r[3]) : "r"(addr));
}
__device__ __forceinline__ void cpa(uint32_t d, const unsigned short* s) {
    asm volatile("cp.async.ca.shared.global [%0], [%1], 16;"
                 :: "r"(d), "l"(__cvta_generic_to_global(s)) : "memory");
}
#define CP_COMMIT() asm volatile("cp.async.commit_group;" ::: "memory")
#define CP_WAIT0()  asm volatile("cp.async.wait_group 0;" ::: "memory")
#define CP_WAIT1()  asm volatile("cp.async.wait_group 1;" ::: "memory")

// ---------------------------------------------------------------------------
// Attention passes (preconverted bf16 operands, cp.async, ldmatrix).
// PASS 1: single-term bf16 S; row sums of E -> g_inv.
// PASS 2: bf16x3 S; W=E*inv written ONCE to wts; O += W*V chained in regs.
// Grid (16 m-tiles, 32 z). 256 thr, warps 4(m) x 2(n). n-tile = 64.
// R12 change: PV inner loop issues terms outermost (acc reuse distance 4).
// ---------------------------------------------------------------------------
template <int PASS>
__global__ __launch_bounds__(256) void attn_kernel(
    const unsigned short* __restrict__ Qhg, const unsigned short* __restrict__ Qlg,
    const unsigned short* __restrict__ Khg, const unsigned short* __restrict__ Klg,
    const unsigned short* __restrict__ Vhg, const unsigned short* __restrict__ Vlg,
    const int* __restrict__ mask, float* __restrict__ wts,
    float* __restrict__ invp, float* __restrict__ Og)
{
    extern __shared__ char smraw[];
    const uint32_t sb = smem_u32(smraw);
    constexpr uint32_t QH = 0;
    constexpr uint32_t QL = 18432;                               // pass2 only
    constexpr uint32_t KB = (PASS == 1) ? 18432u : 36864u;
    constexpr uint32_t KSTR = (PASS == 1) ? 9216u : 18432u;
    constexpr uint32_t VB = 73728;                               // pass2 only
    constexpr uint32_t MK = (PASS == 1) ? 36864u : 110592u;
    __shared__ float rsc[256];

    const int tid = threadIdx.x, lane = tid & 31, wid = tid >> 5;
    const int g = lane >> 2, t4 = lane & 3;
    const int wm0 = (wid >> 1) * 32, wni = wid & 1;
    const int z = blockIdx.y, m0 = blockIdx.x * 128, gb = z >> 4;
    const long long zo = (long long)z * (2048 * 64);
    const long long TT = 2048LL * 2048;

    unsigned char* mk8 = (unsigned char*)(smraw + MK);
    for (int i = tid; i < 2048; i += 256)
        mk8[i] = mask[gb * 2048 + i] ? 0 : 1;

    const uint32_t aRow = (uint32_t)(lane & 15);
    const uint32_t aColB = (uint32_t)((lane >> 4) * 16);
    const uint32_t bRow = (uint32_t)(((lane >> 4) & 1) * 8 + (lane & 7));
    const uint32_t bColB = (uint32_t)(((lane >> 3) & 1) * 16);

#pragma unroll
    for (int i = 0; i < 4; ++i) {
        const int idx = tid + 256 * i, r = idx >> 3, q = idx & 7;
        const long long so = zo + (long long)(m0 + r) * 64 + 8 * q;
        cpa(sb + QH + r * 144 + q * 16, Qhg + so);
        if (PASS == 2) cpa(sb + QL + r * 144 + q * 16, Qlg + so);
    }

    auto issueK = [&](int nt, int buf) {
        const uint32_t kb = sb + KB + (uint32_t)buf * KSTR;
#pragma unroll
        for (int i = 0; i < 2; ++i) {
            const int idx = tid + 256 * i, r = idx >> 3, q = idx & 7;
            const long long so = zo + (long long)(nt * 64 + r) * 64 + 8 * q;
            cpa(kb + r * 144 + q * 16, Khg + so);
            if (PASS == 2) cpa(kb + 9216 + r * 144 + q * 16, Klg + so);
        }
    };
    auto issueV = [&](int nt, int buf) {
        const uint32_t vb = sb + VB + (uint32_t)buf * 18432;
#pragma unroll
        for (int i = 0; i < 2; ++i) {
            const int idx = tid + 256 * i, c = idx >> 3, q = idx & 7;
            const long long so = (long long)(z * 64 + c) * 2048 + nt * 64 + 8 * q;
            cpa(vb + c * 144 + q * 16, Vhg + so);
            cpa(vb + 9216 + c * 144 + q * 16, Vlg + so);
        }
    };

    float iv[2][2];
    float oacc[2][8][4];
    float rs[2][2] = {{0.f, 0.f}, {0.f, 0.f}};
    if (PASS == 2) {
#pragma unroll
        for (int mi = 0; mi < 2; ++mi) {
            iv[mi][0] = invp[z * 2048 + m0 + wm0 + 16 * mi + g];
            iv[mi][1] = invp[z * 2048 + m0 + wm0 + 16 * mi + g + 8];
        }
#pragma unroll
        for (int mi = 0; mi < 2; ++mi)
#pragma unroll
            for (int cf = 0; cf < 8; ++cf)
#pragma unroll
                for (int j = 0; j < 4; ++j) oacc[mi][cf][j] = 0.f;
    }

    issueK(0, 0);
    if (PASS == 2) issueV(0, 0);
    CP_COMMIT();

    for (int nt = 0; nt < 32; ++nt) {
        const int buf = nt & 1;
        if (nt < 31) {
            issueK(nt + 1, buf ^ 1);
            if (PASS == 2) issueV(nt + 1, buf ^ 1);
            CP_COMMIT();
            CP_WAIT1();
        } else {
            CP_WAIT0();
        }
        __syncthreads();

        const uint32_t kh = sb + KB + (uint32_t)buf * KSTR;
        const uint32_t kl = kh + 9216;

        float sacc[2][4][4];
#pragma unroll
        for (int mi = 0; mi < 2; ++mi)
#pragma unroll
            for (int nf = 0; nf < 4; ++nf)
#pragma unroll
                for (int j = 0; j < 4; ++j) sacc[mi][nf][j] = 0.f;

#pragma unroll
        for (int ks = 0; ks < 4; ++ks) {
            const uint32_t ac = (uint32_t)(ks * 32) + aColB;
            const uint32_t bc = (uint32_t)(ks * 32) + bColB;
            uint32_t a0h[4], a1h[4], b0h[4], b1h[4];
            ldsm4(a0h, sb + QH + (wm0 + aRow) * 144 + ac);
            ldsm4(a1h, sb + QH + (wm0 + 16 + aRow) * 144 + ac);
            ldsm4(b0h, kh + (wni * 32 + bRow) * 144 + bc);
            ldsm4(b1h, kh + (wni * 32 + 16 + bRow) * 144 + bc);
            mma_bf16(sacc[0][0], a0h, b0h); mma_bf16(sacc[0][1], a0h, b0h + 2);
            mma_bf16(sacc[0][2], a0h, b1h); mma_bf16(sacc[0][3], a0h, b1h + 2);
            mma_bf16(sacc[1][0], a1h, b0h); mma_bf16(sacc[1][1], a1h, b0h + 2);
            mma_bf16(sacc[1][2], a1h, b1h); mma_bf16(sacc[1][3], a1h, b1h + 2);
            if (PASS == 2) {
                uint32_t a0l[4], a1l[4], b0l[4], b1l[4];
                ldsm4(a0l, sb + QL + (wm0 + aRow) * 144 + ac);
                ldsm4(a1l, sb + QL + (wm0 + 16 + aRow) * 144 + ac);
                ldsm4(b0l, kl + (wni * 32 + bRow) * 144 + bc);
                ldsm4(b1l, kl + (wni * 32 + 16 + bRow) * 144 + bc);
                mma_bf16(sacc[0][0], a0h, b0l); mma_bf16(sacc[0][1], a0h, b0l + 2);
                mma_bf16(sacc[0][2], a0h, b1l); mma_bf16(sacc[0][3], a0h, b1l + 2);
                mma_bf16(sacc[1][0], a1h, b0l); mma_bf16(sacc[1][1], a1h, b0l + 2);
                mma_bf16(sacc[1][2], a1h, b1l); mma_bf16(sacc[1][3], a1h, b1l + 2);
                mma_bf16(sacc[0][0], a0l, b0h); mma_bf16(sacc[0][1], a0l, b0h + 2);
                mma_bf16(sacc[0][2], a0l, b1h); mma_bf16(sacc[0][3], a0l, b1h + 2);
                mma_bf16(sacc[1][0], a1l, b0h); mma_bf16(sacc[1][1], a1l, b0h + 2);
                mma_bf16(sacc[1][2], a1l, b1h); mma_bf16(sacc[1][3], a1l, b1h + 2);
            }
        }

        if (PASS == 1) {
#pragma unroll
            for (int mi = 0; mi < 2; ++mi)
#pragma unroll
                for (int nf = 0; nf < 4; ++nf) {
                    const int n = nt * 64 + wni * 32 + 8 * nf + 2 * t4;
                    const float f0 = (float)mk8[n], f1 = (float)mk8[n + 1];
                    rs[mi][0] += f0 * __expf(0.125f * sacc[mi][nf][0])
                               + f1 * __expf(0.125f * sacc[mi][nf][1]);
                    rs[mi][1] += f0 * __expf(0.125f * sacc[mi][nf][2])
                               + f1 * __expf(0.125f * sacc[mi][nf][3]);
                }
        } else {
            const uint32_t vh = sb + VB + (uint32_t)buf * 18432;
            const uint32_t vl = vh + 9216;
#pragma unroll
            for (int kv = 0; kv < 2; ++kv) {
                uint32_t wh[2][4], wl[2][4];
#pragma unroll
                for (int mi = 0; mi < 2; ++mi) {
#pragma unroll
                    for (int j = 0; j < 2; ++j) {
                        const int nf = 2 * kv + j;
                        const int n = nt * 64 + wni * 32 + 8 * nf + 2 * t4;
                        const float f0 = (float)mk8[n], f1 = (float)mk8[n + 1];
                        const float w0 = f0 * __expf(0.125f * sacc[mi][nf][0]) * iv[mi][0];
                        const float w1 = f1 * __expf(0.125f * sacc[mi][nf][1]) * iv[mi][0];
                        const float w2 = f0 * __expf(0.125f * sacc[mi][nf][2]) * iv[mi][1];
                        const float w3 = f1 * __expf(0.125f * sacc[mi][nf][3]) * iv[mi][1];
                        const int r0 = m0 + wm0 + 16 * mi + g;
                        float* Wp = wts + (long long)z * TT + (long long)r0 * 2048 + n;
                        *(float2*)Wp = make_float2(w0, w1);
                        *(float2*)(Wp + 8LL * 2048) = make_float2(w2, w3);
                        cvt2(w0, w1, wh[mi][2 * j], wl[mi][2 * j]);
                        cvt2(w2, w3, wh[mi][2 * j + 1], wl[mi][2 * j + 1]);
                    }
                }
                const uint32_t vcb = (uint32_t)(wni * 64 + kv * 32) + bColB;
#pragma unroll
                for (int cfp = 0; cfp < 4; ++cfp) {
                    uint32_t vh4[4], vl4[4];
                    ldsm4(vh4, vh + (cfp * 16 + bRow) * 144 + vcb);
                    ldsm4(vl4, vl + (cfp * 16 + bRow) * 144 + vcb);
                    // term-outermost: same-acc reuse distance = 4
#pragma unroll
                    for (int mi = 0; mi < 2; ++mi)
#pragma unroll
                        for (int j = 0; j < 2; ++j)
                            mma_bf16(oacc[mi][2 * cfp + j], wh[mi], vh4 + 2 * j);
#pragma unroll
                    for (int mi = 0; mi < 2; ++mi)
#pragma unroll
                        for (int j = 0; j < 2; ++j)
                            mma_bf16(oacc[mi][2 * cfp + j], wh[mi], vl4 + 2 * j);
#pragma unroll
                    for (int mi = 0; mi < 2; ++mi)
#pragma unroll
                        for (int j = 0; j < 2; ++j)
                            mma_bf16(oacc[mi][2 * cfp + j], wl[mi], vh4 + 2 * j);
                }
            }
        }
        __syncthreads();
    }

    if (PASS == 1) {
#pragma unroll
        for (int mi = 0; mi < 2; ++mi)
#pragma unroll
            for (int j = 0; j < 2; ++j) {
                float v = rs[mi][j];
                v += __shfl_xor_sync(0xffffffffu, v, 1);
                v += __shfl_xor_sync(0xffffffffu, v, 2);
                if (t4 == 0) rsc[(wm0 + 16 * mi + g + 8 * j) * 2 + wni] = v;
            }
        __syncthreads();
        if (tid < 128) {
            const float s = rsc[tid * 2] + rsc[tid * 2 + 1];
            invp[z * 2048 + m0 + tid] = (s > 0.f) ? (1.f / s) : 0.f;
        }
    } else {
        float* Osc = (float*)(smraw + 36864);   // overlay on K buffers
        if (wni == 0) {
#pragma unroll
            for (int mi = 0; mi < 2; ++mi)
#pragma unroll
                for (int cf = 0; cf < 8; ++cf) {
                    const int r0 = wm0 + 16 * mi + g, c = 8 * cf + 2 * t4;
                    *(float2*)(Osc + r0 * 66 + c) = make_float2(oacc[mi][cf][0], oacc[mi][cf][1]);
                    *(float2*)(Osc + (r0 + 8) * 66 + c) = make_float2(oacc[mi][cf][2], oacc[mi][cf][3]);
                }
        }
        __syncthreads();
        if (wni == 1) {
#pragma unroll
            for (int mi = 0; mi < 2; ++mi)
#pragma unroll
                for (int cf = 0; cf < 8; ++cf) {
                    const int r0 = wm0 + 16 * mi + g, c = 8 * cf + 2 * t4;
                    float2 p0 = *(float2*)(Osc + r0 * 66 + c);
                    float2 p1 = *(float2*)(Osc + (r0 + 8) * 66 + c);
                    float* o0 = Og + ((long long)(gb * 2048 + m0 + r0)) * 1024 + (z & 15) * 64 + c;
                    float* o1 = Og + ((long long)(gb * 2048 + m0 + r0 + 8)) * 1024 + (z & 15) * 64 + c;
                    *(float2*)o0 = make_float2(p0.x + oacc[mi][cf][0], p0.y + oacc[mi][cf][1]);
                    *(float2*)o1 = make_float2(p1.x + oacc[mi][cf][2], p1.y + oacc[mi][cf][3]);
                }
        }
    }
}

// ---------------------------------------------------------------------------
// bf16x3 warp-MMA GEMM, 512 threads / 16 warps (4m x 4n), warp tile 32x32.
// C(128 x 128 per CTA) = A(M,K) * B(N,K)^T
// EPI 0: plain fp32 store (out-proj).  EPI 1: QKV routing -> bf16 split arrays.
// R12 change: all fragments preloaded; term loop outermost (reuse dist = 8).
// ---------------------------------------------------------------------------
template <int EPI>
__global__ __launch_bounds__(512, 1) void gemm_mma(
    const float* __restrict__ A, long long lda,
    const float* __restrict__ B0, const float* __restrict__ B1, const float* __restrict__ B2,
    long long ldb,
    float* __restrict__ C, long long ldc, int Kd)
{
    constexpr int SAP = 40;                 // padded stride (bf16), 80 B rows
    constexpr int ASZ = 128 * SAP;
    constexpr int BSZ = 128 * SAP;
    constexpr int STG = 2 * (ASZ + BSZ);

    extern __shared__ unsigned short smem[];
    const uint32_t smB = smem_u32(smem);

    const int tid = threadIdx.x, lane = tid & 31, wid = tid >> 5;
    const int g = lane >> 2, t4 = lane & 3;
    const int wm0 = (wid >> 2) * 32;        // 4 m-warps
    const int wn0 = (wid & 3) * 32;         // 4 n-warps
    const int m0 = blockIdx.y * 128, n0 = blockIdx.x * 128;

    const uint32_t aRow = (uint32_t)(lane & 15);
    const uint32_t aColB = (uint32_t)((lane >> 4) * 16);
    const uint32_t bRow = (uint32_t)(((lane >> 4) & 1) * 8 + (lane & 7));
    const uint32_t bColB = (uint32_t)(((lane >> 3) & 1) * 16);

    const float* Ab = A;
    const float* Bb;
    if (EPI == 1) {
        const int mat = blockIdx.x >> 3;
        const float* Bs = (mat == 0) ? B0 : ((mat == 1) ? B1 : B2);
        Bb = Bs + (long long)((blockIdx.x & 7) * 128) * ldb;
    } else {
        Bb = B0 + (long long)n0 * ldb;
    }

    float acc[2][4][4];
#pragma unroll
    for (int mi = 0; mi < 2; ++mi)
#pragma unroll
        for (int ni = 0; ni < 4; ++ni)
#pragma unroll
            for (int j = 0; j < 4; ++j) acc[mi][ni][j] = 0.f;

    float4 aR[2];
    float4 bR[2];

    auto loadA = [&](int s) {
        const int k0 = s << 5;
#pragma unroll
        for (int i = 0; i < 2; ++i) {
            const int idx = tid + 512 * i, r = idx >> 3, q = idx & 7;
            aR[i] = *(const float4*)(Ab + (long long)(m0 + r) * lda + (k0 + 4 * q));
        }
    };
    auto loadB = [&](int s) {
        const int k0 = s << 5;
#pragma unroll
        for (int i = 0; i < 2; ++i) {
            const int idx = tid + 512 * i, r = idx >> 3, q = idx & 7;
            bR[i] = *(const float4*)(Bb + (long long)r * ldb + (k0 + 4 * q));
        }
    };
    auto stsA = [&](int st) {
        unsigned short* Ah = smem + st * STG;
        unsigned short* Al = Ah + ASZ;
#pragma unroll
        for (int i = 0; i < 2; ++i) {
            const int idx = tid + 512 * i, r = idx >> 3, q = idx & 7;
            uint32_t h01, l01, h23, l23;
            cvt2(aR[i].x, aR[i].y, h01, l01);
            cvt2(aR[i].z, aR[i].w, h23, l23);
            *(uint2*)(Ah + r * SAP + 4 * q) = make_uint2(h01, h23);
            *(uint2*)(Al + r * SAP + 4 * q) = make_uint2(l01, l23);
        }
    };
    auto stsB = [&](int st) {
        unsigned short* Bh = smem + st * STG + 2 * ASZ;
        unsigned short* Bl = Bh + BSZ;
#pragma unroll
        for (int i = 0; i < 2; ++i) {
            const int idx = tid + 512 * i, r = idx >> 3, q = idx & 7;
            uint32_t h01, l01, h23, l23;
            cvt2(bR[i].x, bR[i].y, h01, l01);
            cvt2(bR[i].z, bR[i].w, h23, l23);
            *(uint2*)(Bh + r * SAP + 4 * q) = make_uint2(h01, h23);
            *(uint2*)(Bl + r * SAP + 4 * q) = make_uint2(l01, l23);
        }
    };
    auto compute = [&](int st) {
        const uint32_t AhB = smB + (uint32_t)(st * STG) * 2;
        const uint32_t AlB = AhB + ASZ * 2;
        const uint32_t BhB = AhB + 2 * ASZ * 2;
        const uint32_t BlB = BhB + BSZ * 2;
#pragma unroll
        for (int ks = 0; ks < 2; ++ks) {
            const uint32_t ac = (uint32_t)(ks * 32) + aColB;
            const uint32_t bc = (uint32_t)(ks * 32) + bColB;
            uint32_t ah[2][4], al[2][4], bh[2][4], bl[2][4];
#pragma unroll
            for (int mi = 0; mi < 2; ++mi) {
                ldsm4(ah[mi], AhB + (wm0 + 16 * mi + aRow) * 80 + ac);
                ldsm4(al[mi], AlB + (wm0 + 16 * mi + aRow) * 80 + ac);
            }
#pragma unroll
            for (int nfp = 0; nfp < 2; ++nfp) {
                ldsm4(bh[nfp], BhB + (wn0 + nfp * 16 + bRow) * 80 + bc);
                ldsm4(bl[nfp], BlB + (wn0 + nfp * 16 + bRow) * 80 + bc);
            }
            // term-outermost issue: same-acc reuse distance = 8
#pragma unroll
            for (int mi = 0; mi < 2; ++mi)
#pragma unroll
                for (int nfp = 0; nfp < 2; ++nfp)
#pragma unroll
                    for (int j = 0; j < 2; ++j)
                        mma_bf16(acc[mi][2 * nfp + j], ah[mi], bh[nfp] + 2 * j);
#pragma unroll
            for (int mi = 0; mi < 2; ++mi)
#pragma unroll
                for (int nfp = 0; nfp < 2; ++nfp)
#pragma unroll
                    for (int j = 0; j < 2; ++j)
                        mma_bf16(acc[mi][2 * nfp + j], ah[mi], bl[nfp] + 2 * j);
#pragma unroll
            for (int mi = 0; mi < 2; ++mi)
#pragma unroll
                for (int nfp = 0; nfp < 2; ++nfp)
#pragma unroll
                    for (int j = 0; j < 2; ++j)
                        mma_bf16(acc[mi][2 * nfp + j], al[mi], bh[nfp] + 2 * j);
        }
    };

    const int nS = Kd >> 5;
    loadA(0); loadB(0);
    stsA(0);  stsB(0);
    __syncthreads();
    for (int s = 0; s < nS; ++s) {
        const int st = s & 1;
        if (s + 1 < nS) { loadA(s + 1); loadB(s + 1); }
        compute(st);
        __syncthreads();
        if (s + 1 < nS) { stsA(st ^ 1); stsB(st ^ 1); __syncthreads(); }
    }

#pragma unroll
    for (int mi = 0; mi < 2; ++mi) {
        const int r0 = wm0 + 16 * mi + g, r1 = r0 + 8;
#pragma unroll
        for (int ni = 0; ni < 4; ++ni) {
            const int c = wn0 + 8 * ni + 2 * t4;
            const float v0 = acc[mi][ni][0], v1 = acc[mi][ni][1];
            const float v2 = acc[mi][ni][2], v3 = acc[mi][ni][3];
            if (EPI == 0) {
                *(float2*)(C + (long long)(m0 + r0) * ldc + n0 + c) = make_float2(v0, v1);
                *(float2*)(C + (long long)(m0 + r1) * ldc + n0 + c) = make_float2(v2, v3);
            } else {
                const int nloc = (blockIdx.x & 7) * 128 + c;
                const int h = nloc >> 6, k = nloc & 63;
                const int mat = blockIdx.x >> 3;
                const int mr0 = m0 + r0, b0 = mr0 >> 11, tt0 = mr0 & 2047;
                const int mr1 = m0 + r1, b1 = mr1 >> 11, tt1 = mr1 & 2047;
                uint32_t h01, l01, h23, l23;
                cvt2(v0, v1, h01, l01);
                cvt2(v2, v3, h23, l23);
                if (mat < 2) {
                    unsigned short* dh = (mat == 0) ? g_Qh : g_Kh;
                    unsigned short* dl = (mat == 0) ? g_Ql : g_Kl;
                    const long long o0 = ((long long)((b0 * 16 + h) * 2048 + tt0)) * 64 + k;
                    const long long o1 = ((long long)((b1 * 16 + h) * 2048 + tt1)) * 64 + k;
                    *(uint32_t*)&dh[o0] = h01; *(uint32_t*)&dl[o0] = l01;
                    *(uint32_t*)&dh[o1] = h23; *(uint32_t*)&dl[o1] = l23;
                } else {
                    const long long c0 = ((long long)((b0 * 16 + h) * 64 + k)) * 2048;
                    const long long c1 = c0 + 2048;
                    g_Vth[c0 + tt0] = (unsigned short)(h01 & 0xFFFF);
                    g_Vth[c1 + tt0] = (unsigned short)(h01 >> 16);
                    g_Vtl[c0 + tt0] = (unsigned short)(l01 & 0xFFFF);
                    g_Vtl[c1 + tt0] = (unsigned short)(l01 >> 16);
                    g_Vth[c0 + tt1] = (unsigned short)(h23 & 0xFFFF);
                    g_Vth[c1 + tt1] = (unsigned short)(h23 >> 16);
                    g_Vtl[c0 + tt1] = (unsigned short)(l23 & 0xFFFF);
                    g_Vtl[c1 + tt1] = (unsigned short)(l23 >> 16);
                }
            }
        }
    }
}

// ---------------------------------------------------------------------------
// kernel_launch: x, mask(int32), W_Q, W_K, W_V, W_O -> d_out = [output | weights]
// ---------------------------------------------------------------------------
extern "C" void kernel_launch(void* const* d_in, const int* in_sizes, int n_in,
                              void* d_out, int out_size)
{
    const float* x    = (const float*)d_in[0];
    const int*   mask = (const int*)d_in[1];
    const float* WQ   = (const float*)d_in[2];
    const float* WK   = (const float*)d_in[3];
    const float* WV   = (const float*)d_in[4];
    const float* WO   = (const float*)d_in[5];

    float* out = (float*)d_out;
    float* wts = out + OUT_ELEMS;

    unsigned short *Qh, *Ql, *Kh, *Kl, *Vth, *Vtl;
    float *Op, *invp;
    cudaGetSymbolAddress((void**)&Qh,  g_Qh);
    cudaGetSymbolAddress((void**)&Ql,  g_Ql);
    cudaGetSymbolAddress((void**)&Kh,  g_Kh);
    cudaGetSymbolAddress((void**)&Kl,  g_Kl);
    cudaGetSymbolAddress((void**)&Vth, g_Vth);
    cudaGetSymbolAddress((void**)&Vtl, g_Vtl);
    cudaGetSymbolAddress((void**)&Op,  g_O);
    cudaGetSymbolAddress((void**)&invp, g_inv);

    const int SMG = 2 * 2 * (128 * 40 + 128 * 40) * 2;   // 81920
    const int SM1 = 38912;
    const int SM2 = 112640;
    cudaFuncSetAttribute(gemm_mma<1>, cudaFuncAttributeMaxDynamicSharedMemorySize, SMG);
    cudaFuncSetAttribute(gemm_mma<0>, cudaFuncAttributeMaxDynamicSharedMemorySize, SMG);
    cudaFuncSetAttribute(attn_kernel<1>, cudaFuncAttributeMaxDynamicSharedMemorySize, SM1);
    cudaFuncSetAttribute(attn_kernel<2>, cudaFuncAttributeMaxDynamicSharedMemorySize, SM2);

    // 1) Fused QKV projection -> bf16 split Q,K and transposed V
    gemm_mma<1><<<dim3(24, 32, 1), 512, SMG>>>(
        x, DMODEL, WQ, WK, WV, DMODEL, nullptr, 0, DMODEL);

    // 2) Pass 1: row sums -> inv (single-term bf16 S, zero TT traffic)
    attn_kernel<1><<<dim3(16, 32), 256, SM1>>>(
        Qh, Ql, Kh, Kl, Vth, Vtl, mask, wts, invp, Op);

    // 3) Pass 2: W written once + O = W*V fused (bf16x3)
    attn_kernel<2><<<dim3(16, 32), 256, SM2>>>(
        Qh, Ql, Kh, Kl, Vth, Vtl, mask, wts, invp, Op);

    // 4) Output projection
    gemm_mma<0><<<dim3(8, 32, 1), 512, SMG>>>(
        Op, DMODEL, WO, nullptr, nullptr, DMODEL, out, DMODEL, DMODEL);
}

// round 17
// speedup vs baseline: 1.1170x; 1.0552x over previous
#include <cuda_runtime.h>
#include <cuda_fp16.h>
#include <cstdint>

// ---------------------------------------------------------------------------
// Problem constants
// ---------------------------------------------------------------------------
#define DMODEL 1024
#define NHEADS 16
#define HD     64
#define BATCH  2
#define TSEQ   2048
#define BT     4096
#define NROWS  65536
#define OUT_ELEMS 4194304LL
#define QKV_ELEMS (32 * 2048 * 64)      // 4194304 elements per split array

// Scratch (static device memory; allocation APIs are forbidden)
__device__ unsigned short g_Qh[QKV_ELEMS];   // (z,t,64) fp16 hi
__device__ unsigned short g_Ql[QKV_ELEMS];   // lo
__device__ unsigned short g_Kh[QKV_ELEMS];
__device__ unsigned short g_Kl[QKV_ELEMS];
__device__ unsigned short g_Vth[QKV_ELEMS];  // (z,c,t) fp16 hi (V transposed)
__device__ unsigned short g_Vtl[QKV_ELEMS];
__device__ float g_O[BT * DMODEL];           // (B,T,H*64) fp32
__device__ float g_inv[NROWS];

// ---------------------------------------------------------------------------
// helpers
// ---------------------------------------------------------------------------
__device__ __forceinline__ uint32_t smem_u32(const void* p) {
    uint32_t a;
    asm("{ .reg .u64 t; cvta.to.shared.u64 t, %1; cvt.u32.u64 %0, t; }" : "=r"(a) : "l"(p));
    return a;
}
// fp16 hi/lo split: hp = {lo=f16(x0), hi=f16(x1)}; lp packs the residuals
__device__ __forceinline__ void cvt2(float x0, float x1, uint32_t& hp, uint32_t& lp) {
    __half2 h = __floats2half2_rn(x0, x1);
    hp = *(uint32_t*)&h;
    const float h0 = __half2float(__low2half(h));
    const float h1 = __half2float(__high2half(h));
    __half2 l = __floats2half2_rn(x0 - h0, x1 - h1);
    lp = *(uint32_t*)&l;
}
// single-round fp16 pack (no residual)
__device__ __forceinline__ uint32_t cvt1(float x0, float x1) {
    __half2 h = __floats2half2_rn(x0, x1);
    return *(uint32_t*)&h;
}
__device__ __forceinline__ void mma_16(float* c, const uint32_t* a, const uint32_t* b) {
    asm volatile(
        "mma.sync.aligned.m16n8k16.row.col.f32.f16.f16.f32 "
        "{%0,%1,%2,%3}, {%4,%5,%6,%7}, {%8,%9}, {%0,%1,%2,%3};"
        : "+f"(c[0]), "+f"(c[1]), "+f"(c[2]), "+f"(c[3])
        : "r"(a[0]), "r"(a[1]), "r"(a[2]), "r"(a[3]), "r"(b[0]), "r"(b[1]));
}
__device__ __forceinline__ void ldsm4(uint32_t* r, uint32_t addr) {
    asm volatile("ldmatrix.sync.aligned.m8n8.x4.shared.b16 {%0,%1,%2,%3}, [%4];"
                 : "=r"(r[0]), "=r"(r[1]), "=r"(r[2]), "=r"(r[3]) : "r"(addr));
}
__device__ __forceinline__ void cpa(uint32_t d, const unsigned short* s) {
    asm volatile("cp.async.ca.shared.global [%0], [%1], 16;"
                 :: "r"(d), "l"(__cvta_generic_to_global(s)) : "memory");
}
#define CP_COMMIT() asm volatile("cp.async.commit_group;" ::: "memory")
#define CP_WAIT0()  asm volatile("cp.async.wait_group 0;" ::: "memory")
#define CP_WAIT1()  asm volatile("cp.async.wait_group 1;" ::: "memory")

// ---------------------------------------------------------------------------
// Attention passes (preconverted fp16 operands, cp.async, ldmatrix).
// PASS 1: single-term fp16 S; row sums of E -> g_inv.
// PASS 2: fp16x3 S; W=E*inv written ONCE to wts; O += W*V (2-term: wh only).
// Grid (16 m-tiles, 32 z). 256 thr, warps 4(m) x 2(n). n-tile = 64.
// ---------------------------------------------------------------------------
template <int PASS>
__global__ __launch_bounds__(256) void attn_kernel(
    const unsigned short* __restrict__ Qhg, const unsigned short* __restrict__ Qlg,
    const unsigned short* __restrict__ Khg, const unsigned short* __restrict__ Klg,
    const unsigned short* __restrict__ Vhg, const unsigned short* __restrict__ Vlg,
    const int* __restrict__ mask, float* __restrict__ wts,
    float* __restrict__ invp, float* __restrict__ Og)
{
    extern __shared__ char smraw[];
    const uint32_t sb = smem_u32(smraw);
    constexpr uint32_t QH = 0;
    constexpr uint32_t QL = 18432;                               // pass2 only
    constexpr uint32_t KB = (PASS == 1) ? 18432u : 36864u;
    constexpr uint32_t KSTR = (PASS == 1) ? 9216u : 18432u;
    constexpr uint32_t VB = 73728;                               // pass2 only
    constexpr uint32_t MK = (PASS == 1) ? 36864u : 110592u;
    __shared__ float rsc[256];

    const int tid = threadIdx.x, lane = tid & 31, wid = tid >> 5;
    const int g = lane >> 2, t4 = lane & 3;
    const int wm0 = (wid >> 1) * 32, wni = wid & 1;
    const int z = blockIdx.y, m0 = blockIdx.x * 128, gb = z >> 4;
    const long long zo = (long long)z * (2048 * 64);
    const long long TT = 2048LL * 2048;

    unsigned char* mk8 = (unsigned char*)(smraw + MK);
    for (int i = tid; i < 2048; i += 256)
        mk8[i] = mask[gb * 2048 + i] ? 0 : 1;

    const uint32_t aRow = (uint32_t)(lane & 15);
    const uint32_t aColB = (uint32_t)((lane >> 4) * 16);
    const uint32_t bRow = (uint32_t)(((lane >> 4) & 1) * 8 + (lane & 7));
    const uint32_t bColB = (uint32_t)(((lane >> 3) & 1) * 16);

#pragma unroll
    for (int i = 0; i < 4; ++i) {
        const int idx = tid + 256 * i, r = idx >> 3, q = idx & 7;
        const long long so = zo + (long long)(m0 + r) * 64 + 8 * q;
        cpa(sb + QH + r * 144 + q * 16, Qhg + so);
        if (PASS == 2) cpa(sb + QL + r * 144 + q * 16, Qlg + so);
    }

    auto issueK = [&](int nt, int buf) {
        const uint32_t kb = sb + KB + (uint32_t)buf * KSTR;
#pragma unroll
        for (int i = 0; i < 2; ++i) {
            const int idx = tid + 256 * i, r = idx >> 3, q = idx & 7;
            const long long so = zo + (long long)(nt * 64 + r) * 64 + 8 * q;
            cpa(kb + r * 144 + q * 16, Khg + so);
            if (PASS == 2) cpa(kb + 9216 + r * 144 + q * 16, Klg + so);
        }
    };
    auto issueV = [&](int nt, int buf) {
        const uint32_t vb = sb + VB + (uint32_t)buf * 18432;
#pragma unroll
        for (int i = 0; i < 2; ++i) {
            const int idx = tid + 256 * i, c = idx >> 3, q = idx & 7;
            const long long so = (long long)(z * 64 + c) * 2048 + nt * 64 + 8 * q;
            cpa(vb + c * 144 + q * 16, Vhg + so);
            cpa(vb + 9216 + c * 144 + q * 16, Vlg + so);
        }
    };

    float iv[2][2];
    float oacc[2][8][4];
    float rs[2][2] = {{0.f, 0.f}, {0.f, 0.f}};
    if (PASS == 2) {
#pragma unroll
        for (int mi = 0; mi < 2; ++mi) {
            iv[mi][0] = invp[z * 2048 + m0 + wm0 + 16 * mi + g];
            iv[mi][1] = invp[z * 2048 + m0 + wm0 + 16 * mi + g + 8];
        }
#pragma unroll
        for (int mi = 0; mi < 2; ++mi)
#pragma unroll
            for (int cf = 0; cf < 8; ++cf)
#pragma unroll
                for (int j = 0; j < 4; ++j) oacc[mi][cf][j] = 0.f;
    }

    issueK(0, 0);
    if (PASS == 2) issueV(0, 0);
    CP_COMMIT();

    for (int nt = 0; nt < 32; ++nt) {
        const int buf = nt & 1;
        if (nt < 31) {
            issueK(nt + 1, buf ^ 1);
            if (PASS == 2) issueV(nt + 1, buf ^ 1);
            CP_COMMIT();
            CP_WAIT1();
        } else {
            CP_WAIT0();
        }
        __syncthreads();

        const uint32_t kh = sb + KB + (uint32_t)buf * KSTR;
        const uint32_t kl = kh + 9216;

        float sacc[2][4][4];
#pragma unroll
        for (int mi = 0; mi < 2; ++mi)
#pragma unroll
            for (int nf = 0; nf < 4; ++nf)
#pragma unroll
                for (int j = 0; j < 4; ++j) sacc[mi][nf][j] = 0.f;

#pragma unroll
        for (int ks = 0; ks < 4; ++ks) {
            const uint32_t ac = (uint32_t)(ks * 32) + aColB;
            const uint32_t bc = (uint32_t)(ks * 32) + bColB;
            uint32_t a0h[4], a1h[4], b0h[4], b1h[4];
            ldsm4(a0h, sb + QH + (wm0 + aRow) * 144 + ac);
            ldsm4(a1h, sb + QH + (wm0 + 16 + aRow) * 144 + ac);
            ldsm4(b0h, kh + (wni * 32 + bRow) * 144 + bc);
            ldsm4(b1h, kh + (wni * 32 + 16 + bRow) * 144 + bc);
            mma_16(sacc[0][0], a0h, b0h); mma_16(sacc[0][1], a0h, b0h + 2);
            mma_16(sacc[0][2], a0h, b1h); mma_16(sacc[0][3], a0h, b1h + 2);
            mma_16(sacc[1][0], a1h, b0h); mma_16(sacc[1][1], a1h, b0h + 2);
            mma_16(sacc[1][2], a1h, b1h); mma_16(sacc[1][3], a1h, b1h + 2);
            if (PASS == 2) {
                uint32_t a0l[4], a1l[4], b0l[4], b1l[4];
                ldsm4(a0l, sb + QL + (wm0 + aRow) * 144 + ac);
                ldsm4(a1l, sb + QL + (wm0 + 16 + aRow) * 144 + ac);
                ldsm4(b0l, kl + (wni * 32 + bRow) * 144 + bc);
                ldsm4(b1l, kl + (wni * 32 + 16 + bRow) * 144 + bc);
                mma_16(sacc[0][0], a0h, b0l); mma_16(sacc[0][1], a0h, b0l + 2);
                mma_16(sacc[0][2], a0h, b1l); mma_16(sacc[0][3], a0h, b1l + 2);
                mma_16(sacc[1][0], a1h, b0l); mma_16(sacc[1][1], a1h, b0l + 2);
                mma_16(sacc[1][2], a1h, b1l); mma_16(sacc[1][3], a1h, b1l + 2);
                mma_16(sacc[0][0], a0l, b0h); mma_16(sacc[0][1], a0l, b0h + 2);
                mma_16(sacc[0][2], a0l, b1h); mma_16(sacc[0][3], a0l, b1h + 2);
                mma_16(sacc[1][0], a1l, b0h); mma_16(sacc[1][1], a1l, b0h + 2);
                mma_16(sacc[1][2], a1l, b1h); mma_16(sacc[1][3], a1l, b1h + 2);
            }
        }

        if (PASS == 1) {
#pragma unroll
            for (int mi = 0; mi < 2; ++mi)
#pragma unroll
                for (int nf = 0; nf < 4; ++nf) {
                    const int n = nt * 64 + wni * 32 + 8 * nf + 2 * t4;
                    const float f0 = (float)mk8[n], f1 = (float)mk8[n + 1];
                    rs[mi][0] += f0 * __expf(0.125f * sacc[mi][nf][0])
                               + f1 * __expf(0.125f * sacc[mi][nf][1]);
                    rs[mi][1] += f0 * __expf(0.125f * sacc[mi][nf][2])
                               + f1 * __expf(0.125f * sacc[mi][nf][3]);
                }
        } else {
            const uint32_t vh = sb + VB + (uint32_t)buf * 18432;
            const uint32_t vl = vh + 9216;
#pragma unroll
            for (int kv = 0; kv < 2; ++kv) {
                uint32_t wh[2][4];
#pragma unroll
                for (int mi = 0; mi < 2; ++mi) {
#pragma unroll
                    for (int j = 0; j < 2; ++j) {
                        const int nf = 2 * kv + j;
                        const int n = nt * 64 + wni * 32 + 8 * nf + 2 * t4;
                        const float f0 = (float)mk8[n], f1 = (float)mk8[n + 1];
                        const float w0 = f0 * __expf(0.125f * sacc[mi][nf][0]) * iv[mi][0];
                        const float w1 = f1 * __expf(0.125f * sacc[mi][nf][1]) * iv[mi][0];
                        const float w2 = f0 * __expf(0.125f * sacc[mi][nf][2]) * iv[mi][1];
                        const float w3 = f1 * __expf(0.125f * sacc[mi][nf][3]) * iv[mi][1];
                        const int r0 = m0 + wm0 + 16 * mi + g;
                        float* Wp = wts + (long long)z * TT + (long long)r0 * 2048 + n;
                        *(float2*)Wp = make_float2(w0, w1);
                        *(float2*)(Wp + 8LL * 2048) = make_float2(w2, w3);
                        wh[mi][2 * j]     = cvt1(w0, w1);
                        wh[mi][2 * j + 1] = cvt1(w2, w3);
                    }
                }
                const uint32_t vcb = (uint32_t)(wni * 64 + kv * 32) + bColB;
#pragma unroll
                for (int cfp = 0; cfp < 4; ++cfp) {
                    uint32_t vh4[4], vl4[4];
                    ldsm4(vh4, vh + (cfp * 16 + bRow) * 144 + vcb);
                    ldsm4(vl4, vl + (cfp * 16 + bRow) * 144 + vcb);
                    // 2-term PV: wh*(vh + vl); w_lo term dropped (~2^-11 rel)
#pragma unroll
                    for (int mi = 0; mi < 2; ++mi)
#pragma unroll
                        for (int j = 0; j < 2; ++j)
                            mma_16(oacc[mi][2 * cfp + j], wh[mi], vh4 + 2 * j);
#pragma unroll
                    for (int mi = 0; mi < 2; ++mi)
#pragma unroll
                        for (int j = 0; j < 2; ++j)
                            mma_16(oacc[mi][2 * cfp + j], wh[mi], vl4 + 2 * j);
                }
            }
        }
        __syncthreads();
    }

    if (PASS == 1) {
#pragma unroll
        for (int mi = 0; mi < 2; ++mi)
#pragma unroll
            for (int j = 0; j < 2; ++j) {
                float v = rs[mi][j];
                v += __shfl_xor_sync(0xffffffffu, v, 1);
                v += __shfl_xor_sync(0xffffffffu, v, 2);
                if (t4 == 0) rsc[(wm0 + 16 * mi + g + 8 * j) * 2 + wni] = v;
            }
        __syncthreads();
        if (tid < 128) {
            const float s = rsc[tid * 2] + rsc[tid * 2 + 1];
            invp[z * 2048 + m0 + tid] = (s > 0.f) ? (1.f / s) : 0.f;
        }
    } else {
        float* Osc = (float*)(smraw + 36864);   // overlay on K buffers
        if (wni == 0) {
#pragma unroll
            for (int mi = 0; mi < 2; ++mi)
#pragma unroll
                for (int cf = 0; cf < 8; ++cf) {
                    const int r0 = wm0 + 16 * mi + g, c = 8 * cf + 2 * t4;
                    *(float2*)(Osc + r0 * 66 + c) = make_float2(oacc[mi][cf][0], oacc[mi][cf][1]);
                    *(float2*)(Osc + (r0 + 8) * 66 + c) = make_float2(oacc[mi][cf][2], oacc[mi][cf][3]);
                }
        }
        __syncthreads();
        if (wni == 1) {
#pragma unroll
            for (int mi = 0; mi < 2; ++mi)
#pragma unroll
                for (int cf = 0; cf < 8; ++cf) {
                    const int r0 = wm0 + 16 * mi + g, c = 8 * cf + 2 * t4;
                    float2 p0 = *(float2*)(Osc + r0 * 66 + c);
                    float2 p1 = *(float2*)(Osc + (r0 + 8) * 66 + c);
                    float* o0 = Og + ((long long)(gb * 2048 + m0 + r0)) * 1024 + (z & 15) * 64 + c;
                    float* o1 = Og + ((long long)(gb * 2048 + m0 + r0 + 8)) * 1024 + (z & 15) * 64 + c;
                    *(float2*)o0 = make_float2(p0.x + oacc[mi][cf][0], p0.y + oacc[mi][cf][1]);
                    *(float2*)o1 = make_float2(p1.x + oacc[mi][cf][2], p1.y + oacc[mi][cf][3]);
                }
        }
    }
}

// ---------------------------------------------------------------------------
// fp16x3 warp-MMA GEMM, 512 threads / 16 warps (4m x 4n), warp tile 32x32.
// C(128 x 128 per CTA) = A(M,K) * B(N,K)^T
// EPI 0: plain fp32 store (out-proj).  EPI 1: QKV routing -> fp16 split arrays.
// ---------------------------------------------------------------------------
template <int EPI>
__global__ __launch_bounds__(512, 1) void gemm_mma(
    const float* __restrict__ A, long long lda,
    const float* __restrict__ B0, const float* __restrict__ B1, const float* __restrict__ B2,
    long long ldb,
    float* __restrict__ C, long long ldc, int Kd)
{
    constexpr int SAP = 40;                 // padded stride (fp16), 80 B rows
    constexpr int ASZ = 128 * SAP;
    constexpr int BSZ = 128 * SAP;
    constexpr int STG = 2 * (ASZ + BSZ);

    extern __shared__ unsigned short smem[];
    const uint32_t smB = smem_u32(smem);

    const int tid = threadIdx.x, lane = tid & 31, wid = tid >> 5;
    const int g = lane >> 2, t4 = lane & 3;
    const int wm0 = (wid >> 2) * 32;        // 4 m-warps
    const int wn0 = (wid & 3) * 32;         // 4 n-warps
    const int m0 = blockIdx.y * 128, n0 = blockIdx.x * 128;

    const uint32_t aRow = (uint32_t)(lane & 15);
    const uint32_t aColB = (uint32_t)((lane >> 4) * 16);
    const uint32_t bRow = (uint32_t)(((lane >> 4) & 1) * 8 + (lane & 7));
    const uint32_t bColB = (uint32_t)(((lane >> 3) & 1) * 16);

    const float* Ab = A;
    const float* Bb;
    if (EPI == 1) {
        const int mat = blockIdx.x >> 3;
        const float* Bs = (mat == 0) ? B0 : ((mat == 1) ? B1 : B2);
        Bb = Bs + (long long)((blockIdx.x & 7) * 128) * ldb;
    } else {
        Bb = B0 + (long long)n0 * ldb;
    }

    float acc[2][4][4];
#pragma unroll
    for (int mi = 0; mi < 2; ++mi)
#pragma unroll
        for (int ni = 0; ni < 4; ++ni)
#pragma unroll
            for (int j = 0; j < 4; ++j) acc[mi][ni][j] = 0.f;

    float4 aR[2];
    float4 bR[2];

    auto loadA = [&](int s) {
        const int k0 = s << 5;
#pragma unroll
        for (int i = 0; i < 2; ++i) {
            const int idx = tid + 512 * i, r = idx >> 3, q = idx & 7;
            aR[i] = *(const float4*)(Ab + (long long)(m0 + r) * lda + (k0 + 4 * q));
        }
    };
    auto loadB = [&](int s) {
        const int k0 = s << 5;
#pragma unroll
        for (int i = 0; i < 2; ++i) {
            const int idx = tid + 512 * i, r = idx >> 3, q = idx & 7;
            bR[i] = *(const float4*)(Bb + (long long)r * ldb + (k0 + 4 * q));
        }
    };
    auto stsA = [&](int st) {
        unsigned short* Ah = smem + st * STG;
        unsigned short* Al = Ah + ASZ;
#pragma unroll
        for (int i = 0; i < 2; ++i) {
            const int idx = tid + 512 * i, r = idx >> 3, q = idx & 7;
            uint32_t h01, l01, h23, l23;
            cvt2(aR[i].x, aR[i].y, h01, l01);
            cvt2(aR[i].z, aR[i].w, h23, l23);
            *(uint2*)(Ah + r * SAP + 4 * q) = make_uint2(h01, h23);
            *(uint2*)(Al + r * SAP + 4 * q) = make_uint2(l01, l23);
        }
    };
    auto stsB = [&](int st) {
        unsigned short* Bh = smem + st * STG + 2 * ASZ;
        unsigned short* Bl = Bh + BSZ;
#pragma unroll
        for (int i = 0; i < 2; ++i) {
            const int idx = tid + 512 * i, r = idx >> 3, q = idx & 7;
            uint32_t h01, l01, h23, l23;
            cvt2(bR[i].x, bR[i].y, h01, l01);
            cvt2(bR[i].z, bR[i].w, h23, l23);
            *(uint2*)(Bh + r * SAP + 4 * q) = make_uint2(h01, h23);
            *(uint2*)(Bl + r * SAP + 4 * q) = make_uint2(l01, l23);
        }
    };
    auto compute = [&](int st) {
        const uint32_t AhB = smB + (uint32_t)(st * STG) * 2;
        const uint32_t AlB = AhB + ASZ * 2;
        const uint32_t BhB = AhB + 2 * ASZ * 2;
        const uint32_t BlB = BhB + BSZ * 2;
#pragma unroll
        for (int ks = 0; ks < 2; ++ks) {
            const uint32_t ac = (uint32_t)(ks * 32) + aColB;
            const uint32_t bc = (uint32_t)(ks * 32) + bColB;
            uint32_t ah[2][4], al[2][4], bh[2][4], bl[2][4];
#pragma unroll
            for (int mi = 0; mi < 2; ++mi) {
                ldsm4(ah[mi], AhB + (wm0 + 16 * mi + aRow) * 80 + ac);
                ldsm4(al[mi], AlB + (wm0 + 16 * mi + aRow) * 80 + ac);
            }
#pragma unroll
            for (int nfp = 0; nfp < 2; ++nfp) {
                ldsm4(bh[nfp], BhB + (wn0 + nfp * 16 + bRow) * 80 + bc);
                ldsm4(bl[nfp], BlB + (wn0 + nfp * 16 + bRow) * 80 + bc);
            }
#pragma unroll
            for (int mi = 0; mi < 2; ++mi)
#pragma unroll
                for (int nfp = 0; nfp < 2; ++nfp)
#pragma unroll
                    for (int j = 0; j < 2; ++j)
                        mma_16(acc[mi][2 * nfp + j], ah[mi], bh[nfp] + 2 * j);
#pragma unroll
            for (int mi = 0; mi < 2; ++mi)
#pragma unroll
                for (int nfp = 0; nfp < 2; ++nfp)
#pragma unroll
                    for (int j = 0; j < 2; ++j)
                        mma_16(acc[mi][2 * nfp + j], ah[mi], bl[nfp] + 2 * j);
#pragma unroll
            for (int mi = 0; mi < 2; ++mi)
#pragma unroll
                for (int nfp = 0; nfp < 2; ++nfp)
#pragma unroll
                    for (int j = 0; j < 2; ++j)
                        mma_16(acc[mi][2 * nfp + j], al[mi], bh[nfp] + 2 * j);
        }
    };

    const int nS = Kd >> 5;
    loadA(0); loadB(0);
    stsA(0);  stsB(0);
    __syncthreads();
    for (int s = 0; s < nS; ++s) {
        const int st = s & 1;
        if (s + 1 < nS) { loadA(s + 1); loadB(s + 1); }
        compute(st);
        __syncthreads();
        if (s + 1 < nS) { stsA(st ^ 1); stsB(st ^ 1); __syncthreads(); }
    }

#pragma unroll
    for (int mi = 0; mi < 2; ++mi) {
        const int r0 = wm0 + 16 * mi + g, r1 = r0 + 8;
#pragma unroll
        for (int ni = 0; ni < 4; ++ni) {
            const int c = wn0 + 8 * ni + 2 * t4;
            const float v0 = acc[mi][ni][0], v1 = acc[mi][ni][1];
            const float v2 = acc[mi][ni][2], v3 = acc[mi][ni][3];
            if (EPI == 0) {
                *(float2*)(C + (long long)(m0 + r0) * ldc + n0 + c) = make_float2(v0, v1);
                *(float2*)(C + (long long)(m0 + r1) * ldc + n0 + c) = make_float2(v2, v3);
            } else {
                const int nloc = (blockIdx.x & 7) * 128 + c;
                const int h = nloc >> 6, k = nloc & 63;
                const int mat = blockIdx.x >> 3;
                const int mr0 = m0 + r0, b0 = mr0 >> 11, tt0 = mr0 & 2047;
                const int mr1 = m0 + r1, b1 = mr1 >> 11, tt1 = mr1 & 2047;
                uint32_t h01, l01, h23, l23;
                cvt2(v0, v1, h01, l01);
                cvt2(v2, v3, h23, l23);
                if (mat < 2) {
                    unsigned short* dh = (mat == 0) ? g_Qh : g_Kh;
                    unsigned short* dl = (mat == 0) ? g_Ql : g_Kl;
                    const long long o0 = ((long long)((b0 * 16 + h) * 2048 + tt0)) * 64 + k;
                    const long long o1 = ((long long)((b1 * 16 + h) * 2048 + tt1)) * 64 + k;
                    *(uint32_t*)&dh[o0] = h01; *(uint32_t*)&dl[o0] = l01;
                    *(uint32_t*)&dh[o1] = h23; *(uint32_t*)&dl[o1] = l23;
                } else {
                    const long long c0 = ((long long)((b0 * 16 + h) * 64 + k)) * 2048;
                    const long long c1 = c0 + 2048;
                    g_Vth[c0 + tt0] = (unsigned short)(h01 & 0xFFFF);
                    g_Vth[c1 + tt0] = (unsigned short)(h01 >> 16);
                    g_Vtl[c0 + tt0] = (unsigned short)(l01 & 0xFFFF);
                    g_Vtl[c1 + tt0] = (unsigned short)(l01 >> 16);
                    g_Vth[c0 + tt1] = (unsigned short)(h23 & 0xFFFF);
                    g_Vth[c1 + tt1] = (unsigned short)(h23 >> 16);
                    g_Vtl[c0 + tt1] = (unsigned short)(l23 & 0xFFFF);
                    g_Vtl[c1 + tt1] = (unsigned short)(l23 >> 16);
                }
            }
        }
    }
}

// ---------------------------------------------------------------------------
// kernel_launch: x, mask(int32), W_Q, W_K, W_V, W_O -> d_out = [output | weights]
// ---------------------------------------------------------------------------
extern "C" void kernel_launch(void* const* d_in, const int* in_sizes, int n_in,
                              void* d_out, int out_size)
{
    const float* x    = (const float*)d_in[0];
    const int*   mask = (const int*)d_in[1];
    const float* WQ   = (const float*)d_in[2];
    const float* WK   = (const float*)d_in[3];
    const float* WV   = (const float*)d_in[4];
    const float* WO   = (const float*)d_in[5];

    float* out = (float*)d_out;
    float* wts = out + OUT_ELEMS;

    unsigned short *Qh, *Ql, *Kh, *Kl, *Vth, *Vtl;
    float *Op, *invp;
    cudaGetSymbolAddress((void**)&Qh,  g_Qh);
    cudaGetSymbolAddress((void**)&Ql,  g_Ql);
    cudaGetSymbolAddress((void**)&Kh,  g_Kh);
    cudaGetSymbolAddress((void**)&Kl,  g_Kl);
    cudaGetSymbolAddress((void**)&Vth, g_Vth);
    cudaGetSymbolAddress((void**)&Vtl, g_Vtl);
    cudaGetSymbolAddress((void**)&Op,  g_O);
    cudaGetSymbolAddress((void**)&invp, g_inv);

    const int SMG = 2 * 2 * (128 * 40 + 128 * 40) * 2;   // 81920
    const int SM1 = 38912;
    const int SM2 = 112640;
    cudaFuncSetAttribute(gemm_mma<1>, cudaFuncAttributeMaxDynamicSharedMemorySize, SMG);
    cudaFuncSetAttribute(gemm_mma<0>, cudaFuncAttributeMaxDynamicSharedMemorySize, SMG);
    cudaFuncSetAttribute(attn_kernel<1>, cudaFuncAttributeMaxDynamicSharedMemorySize, SM1);
    cudaFuncSetAttribute(attn_kernel<2>, cudaFuncAttributeMaxDynamicSharedMemorySize, SM2);

    // 1) Fused QKV projection -> fp16 split Q,K and transposed V
    gemm_mma<1><<<dim3(24, 32, 1), 512, SMG>>>(
        x, DMODEL, WQ, WK, WV, DMODEL, nullptr, 0, DMODEL);

    // 2) Pass 1: row sums -> inv (single-term fp16 S, zero TT traffic)
    attn_kernel<1><<<dim3(16, 32), 256, SM1>>>(
        Qh, Ql, Kh, Kl, Vth, Vtl, mask, wts, invp, Op);

    // 3) Pass 2: W written once + O = W*V fused (fp16x3 S, 2-term PV)
    attn_kernel<2><<<dim3(16, 32), 256, SM2>>>(
        Qh, Ql, Kh, Kl, Vth, Vtl, mask, wts, invp, Op);

    // 4) Output projection
    gemm_mma<0><<<dim3(8, 32, 1), 512, SMG>>>(
        Op, DMODEL, WO, nullptr, nullptr, DMODEL, out, DMODEL, DMODEL);
}